// round 1
// baseline (speedup 1.0000x reference)
#include <cuda_runtime.h>
#include <cuda_bf16.h>

// ---------------------------------------------------------------------------
// SignatureToLogSignature: log of a depth-6, 8-channel truncated signature,
// projected onto Lyndon words ('words' mode).
//
// log_k[w] = sum_{n=1..k} c_n * sum_{compositions k=i1+..+in}
//                 prod_t x_{i_t}[chunk_t(w)],   c_n = (-1)^{n+1}/n.
// Computed per-output-element with a composition DP; only Lyndon indices
// are evaluated (x6 is gathered at Lyndon words only).
// ---------------------------------------------------------------------------

#define CHANNELS 8
#define DEPTH    6
#define BATCH    128

// flat offsets of levels 1..6 inside one signature row, and total
__device__ __host__ __forceinline__ int off_of_level_host(int L);
static const int H_OFF[7] = {0, 8, 72, 584, 4680, 37448, 299592};
#define SIG_SIZE  299592
#define NLYN      51360
#define SMEM_X14  4680      // levels 1..4 staged in shared memory

#define NFLAT   SIG_SIZE
#define CHUNK   64
#define NCHUNK  ((NFLAT + CHUNK - 1) / CHUNK)   // 4682

__device__ int d_counts[NCHUNK];
__device__ int d_offsets[NCHUNK];
__device__ int d_table[NLYN];

// ---------------------------------------------------------------------------
// Lyndon test on a flat tensor-algebra index
// ---------------------------------------------------------------------------
__device__ __forceinline__ bool is_lyndon(int f) {
    int L; unsigned j;
    if      (f < 8)     { L = 1; j = (unsigned)f; }
    else if (f < 72)    { L = 2; j = (unsigned)(f - 8); }
    else if (f < 584)   { L = 3; j = (unsigned)(f - 72); }
    else if (f < 4680)  { L = 4; j = (unsigned)(f - 584); }
    else if (f < 37448) { L = 5; j = (unsigned)(f - 4680); }
    else                { L = 6; j = (unsigned)(f - 37448); }
    const unsigned mask = (1u << (3 * L)) - 1u;
    #pragma unroll 5
    for (int r = 1; r < L; ++r) {
        unsigned rot = ((j << (3 * r)) | (j >> (3 * (L - r)))) & mask;
        if (rot <= j) return false;   // must be STRICTLY smallest rotation
    }
    return true;
}

__global__ void k_count() {
    int c = blockIdx.x * blockDim.x + threadIdx.x;
    if (c >= NCHUNK) return;
    int f0 = c * CHUNK;
    int f1 = min(f0 + CHUNK, NFLAT);
    int s = 0;
    for (int f = f0; f < f1; ++f) s += (int)is_lyndon(f);
    d_counts[c] = s;
}

__global__ void k_scan() {
    __shared__ int buf[1024];
    const int t = threadIdx.x;
    const int PER = 5;                 // 1024*5 = 5120 >= NCHUNK
    int loc[PER];
    int s = 0;
    #pragma unroll
    for (int k = 0; k < PER; ++k) {
        int i = t * PER + k;
        int v = (i < NCHUNK) ? d_counts[i] : 0;
        loc[k] = s; s += v;
    }
    buf[t] = s;
    __syncthreads();
    for (int off = 1; off < 1024; off <<= 1) {
        int v = (t >= off) ? buf[t - off] : 0;
        __syncthreads();
        buf[t] += v;
        __syncthreads();
    }
    int pre = (t > 0) ? buf[t - 1] : 0;
    #pragma unroll
    for (int k = 0; k < PER; ++k) {
        int i = t * PER + k;
        if (i < NCHUNK) d_offsets[i] = pre + loc[k];
    }
}

__global__ void k_fill() {
    int c = blockIdx.x * blockDim.x + threadIdx.x;
    if (c >= NCHUNK) return;
    int p = d_offsets[c];
    int f0 = c * CHUNK;
    int f1 = min(f0 + CHUNK, NFLAT);
    for (int f = f0; f < f1; ++f)
        if (is_lyndon(f)) d_table[p++] = f;
}

// ---------------------------------------------------------------------------
// Composition DP over one word of length L.
//   P[i][n] = sum over compositions of first i letters into n parts of the
//             product of level values.   result = sum_n c_n * P[L][n].
// Fully unrolled -> all arrays in registers.
// ---------------------------------------------------------------------------
template <int L>
__device__ __forceinline__ float eval_word(const float* __restrict__ sm,
                                           const float* __restrict__ g5,
                                           const float* __restrict__ g6,
                                           unsigned j) {
    float g50 = 0.f, g51 = 0.f, g60 = 0.f;
    if (L >= 5) g50 = __ldg(g5 + ((j >> (3 * (L - 5))) & 0x7FFFu));
    if (L == 6) { g51 = __ldg(g5 + (j & 0x7FFFu)); g60 = __ldg(g6 + j); }

    float P[L + 1][L + 1];
    #pragma unroll
    for (int i = 1; i <= L; ++i)
        #pragma unroll
        for (int n = 1; n <= i; ++n) P[i][n] = 0.0f;

    #pragma unroll
    for (int i = 1; i <= L; ++i) {
        #pragma unroll
        for (int a = 0; a < i; ++a) {
            const int len = i - a;                         // compile-time after unroll
            const unsigned idx = (j >> (3 * (L - i))) & ((1u << (3 * len)) - 1u);
            float s;
            if      (len == 1) s = sm[idx];
            else if (len == 2) s = sm[8 + idx];
            else if (len == 3) s = sm[72 + idx];
            else if (len == 4) s = sm[584 + idx];
            else if (len == 5) s = (a == 0) ? g50 : g51;
            else               s = g60;
            if (a == 0) {
                P[i][1] += s;                               // P[0][0] == 1
            } else {
                #pragma unroll
                for (int n = 2; n <= a + 1; ++n)
                    P[i][n] += P[a][n - 1] * s;
            }
        }
    }
    const float c[7] = {0.f, 1.f, -0.5f, 1.f / 3.f, -0.25f, 0.2f, -1.f / 6.f};
    float r = 0.f;
    #pragma unroll
    for (int n = 1; n <= L; ++n) r += c[n] * P[L][n];
    return r;
}

// ---------------------------------------------------------------------------
// Main kernel: grid = (32 m-interleaves, BATCH), 256 threads.
// ---------------------------------------------------------------------------
__global__ void __launch_bounds__(256)
logsig_main(const float* __restrict__ sig, float* __restrict__ out) {
    __shared__ float sm[SMEM_X14];
    const int b = blockIdx.y;
    const float* __restrict__ row = sig + (size_t)b * SIG_SIZE;
    for (int i = threadIdx.x; i < SMEM_X14; i += blockDim.x) sm[i] = row[i];
    __syncthreads();

    const float* __restrict__ g5 = row + 4680;
    const float* __restrict__ g6 = row + 37448;
    float* __restrict__ orow = out + (size_t)b * NLYN;

    #pragma unroll 1
    for (int it = 0; it < 7; ++it) {
        int m = it * (32 * 256) + blockIdx.x * 256 + threadIdx.x;
        if (m >= NLYN) break;
        int f = d_table[m];
        float r;
        if      (f < 8)     r = eval_word<1>(sm, g5, g6, (unsigned)f);
        else if (f < 72)    r = eval_word<2>(sm, g5, g6, (unsigned)(f - 8));
        else if (f < 584)   r = eval_word<3>(sm, g5, g6, (unsigned)(f - 72));
        else if (f < 4680)  r = eval_word<4>(sm, g5, g6, (unsigned)(f - 584));
        else if (f < 37448) r = eval_word<5>(sm, g5, g6, (unsigned)(f - 4680));
        else                r = eval_word<6>(sm, g5, g6, (unsigned)(f - 37448));
        orow[m] = r;
    }
}

// ---------------------------------------------------------------------------
extern "C" void kernel_launch(void* const* d_in, const int* in_sizes, int n_in,
                              void* d_out, int out_size) {
    const float* sig = (const float*)d_in[0];
    float* out = (float*)d_out;

    k_count<<<(NCHUNK + 255) / 256, 256>>>();
    k_scan<<<1, 1024>>>();
    k_fill<<<(NCHUNK + 255) / 256, 256>>>();

    dim3 grid(32, BATCH);
    logsig_main<<<grid, 256>>>(sig, out);
}

// round 4
// speedup vs baseline: 1.6184x; 1.6184x over previous
#include <cuda_runtime.h>
#include <cuda_bf16.h>

// ---------------------------------------------------------------------------
// SignatureToLogSignature: log of a depth-6, 8-channel truncated signature,
// projected onto Lyndon words ('words' mode).
//
// log_k[w] = sum_{n=1..k} c_n * sum_{compositions k=i1+..+in}
//                 prod_t x_{i_t}[chunk_t(w)],   c_n = (-1)^{n+1}/n.
// Computed per-output-element with a composition DP; only Lyndon indices
// are evaluated (x6 is gathered at Lyndon words only).
// ---------------------------------------------------------------------------

#define CHANNELS 8
#define DEPTH    6
#define BATCH    128

#define SIG_SIZE  299592
#define NLYN      51360
#define SMEM_X14  4680      // levels 1..4 staged in shared memory

#define NFLAT   SIG_SIZE
#define CH2     8
#define NCH2    (NFLAT / CH2)                  // 37449 (exact)
#define K1_BLK  ((NCH2 + 255) / 256)           // 147

__device__ int d_blocksum[K1_BLK];
__device__ int d_blockoff[K1_BLK];
__device__ int d_table[NLYN];

// ---------------------------------------------------------------------------
// Lyndon test on a flat tensor-algebra index
// ---------------------------------------------------------------------------
__device__ __forceinline__ bool is_lyndon(int f) {
    int L; unsigned j;
    if      (f < 8)     { L = 1; j = (unsigned)f; }
    else if (f < 72)    { L = 2; j = (unsigned)(f - 8); }
    else if (f < 584)   { L = 3; j = (unsigned)(f - 72); }
    else if (f < 4680)  { L = 4; j = (unsigned)(f - 584); }
    else if (f < 37448) { L = 5; j = (unsigned)(f - 4680); }
    else                { L = 6; j = (unsigned)(f - 37448); }
    const unsigned mask = (1u << (3 * L)) - 1u;
    #pragma unroll 5
    for (int r = 1; r < L; ++r) {
        unsigned rot = ((j << (3 * r)) | (j >> (3 * (L - r)))) & mask;
        if (rot <= j) return false;   // must be STRICTLY smallest rotation
    }
    return true;
}

__device__ __forceinline__ int count_chunk(int c) {
    int f0 = c * CH2;
    int s = 0;
    #pragma unroll
    for (int k = 0; k < CH2; ++k) {
        int f = f0 + k;
        if (f < NFLAT) s += (int)is_lyndon(f);
    }
    return s;
}

// K1: per-thread count + block reduce -> d_blocksum[block]
__global__ void __launch_bounds__(256) k_count() {
    __shared__ int red[256];
    int c = blockIdx.x * 256 + threadIdx.x;
    int s = (c < NCH2) ? count_chunk(c) : 0;
    red[threadIdx.x] = s;
    __syncthreads();
    #pragma unroll
    for (int off = 128; off > 0; off >>= 1) {
        if (threadIdx.x < off) red[threadIdx.x] += red[threadIdx.x + off];
        __syncthreads();
    }
    if (threadIdx.x == 0) d_blocksum[blockIdx.x] = red[0];
}

// K2: exclusive scan of the 147 block sums (single block)
__global__ void __launch_bounds__(256) k_scanb() {
    __shared__ int buf[256];
    int t = threadIdx.x;
    int v = (t < K1_BLK) ? d_blocksum[t] : 0;
    buf[t] = v;
    __syncthreads();
    #pragma unroll
    for (int off = 1; off < 256; off <<= 1) {
        int u = (t >= off) ? buf[t - off] : 0;
        __syncthreads();
        buf[t] += u;
        __syncthreads();
    }
    if (t < K1_BLK) d_blockoff[t] = buf[t] - v;   // exclusive
}

// K3: recompute counts, block-local exclusive scan, global offset, fill
__global__ void __launch_bounds__(256) k_fill() {
    __shared__ int buf[256];
    int t = threadIdx.x;
    int c = blockIdx.x * 256 + t;
    int s = (c < NCH2) ? count_chunk(c) : 0;
    buf[t] = s;
    __syncthreads();
    #pragma unroll
    for (int off = 1; off < 256; off <<= 1) {
        int u = (t >= off) ? buf[t - off] : 0;
        __syncthreads();
        buf[t] += u;
        __syncthreads();
    }
    if (c >= NCH2) return;
    int p = d_blockoff[blockIdx.x] + buf[t] - s;  // global exclusive prefix
    int f0 = c * CH2;
    #pragma unroll
    for (int k = 0; k < CH2; ++k) {
        int f = f0 + k;
        if (f < NFLAT && is_lyndon(f)) d_table[p++] = f;
    }
}

// ---------------------------------------------------------------------------
// Composition DP over one word of length L.
//   P[i][n] = sum over compositions of first i letters into n parts of the
//             product of level values.   result = sum_n c_n * P[L][n].
// Fully unrolled -> all arrays in registers.
// ---------------------------------------------------------------------------
template <int L>
__device__ __forceinline__ float eval_word(const float* __restrict__ sm,
                                           const float* __restrict__ g5,
                                           const float* __restrict__ g6,
                                           unsigned j) {
    float g50 = 0.f, g51 = 0.f, g60 = 0.f;
    if (L >= 5) g50 = __ldg(g5 + ((j >> (3 * (L - 5))) & 0x7FFFu));
    if (L == 6) { g51 = __ldg(g5 + (j & 0x7FFFu)); g60 = __ldg(g6 + j); }

    float P[L + 1][L + 1];
    #pragma unroll
    for (int i = 1; i <= L; ++i)
        #pragma unroll
        for (int n = 1; n <= i; ++n) P[i][n] = 0.0f;

    #pragma unroll
    for (int i = 1; i <= L; ++i) {
        #pragma unroll
        for (int a = 0; a < i; ++a) {
            const int len = i - a;                         // compile-time after unroll
            const unsigned idx = (j >> (3 * (L - i))) & ((1u << (3 * len)) - 1u);
            float s;
            if      (len == 1) s = sm[idx];
            else if (len == 2) s = sm[8 + idx];
            else if (len == 3) s = sm[72 + idx];
            else if (len == 4) s = sm[584 + idx];
            else if (len == 5) s = (a == 0) ? g50 : g51;
            else               s = g60;
            if (a == 0) {
                P[i][1] += s;                               // P[0][0] == 1
            } else {
                #pragma unroll
                for (int n = 2; n <= a + 1; ++n)
                    P[i][n] += P[a][n - 1] * s;
            }
        }
    }
    const float c[7] = {0.f, 1.f, -0.5f, 1.f / 3.f, -0.25f, 0.2f, -1.f / 6.f};
    float r = 0.f;
    #pragma unroll
    for (int n = 1; n <= L; ++n) r += c[n] * P[L][n];
    return r;
}

// ---------------------------------------------------------------------------
// Main kernel: grid = (32 m-interleaves, BATCH), 256 threads.
// ---------------------------------------------------------------------------
__global__ void __launch_bounds__(256)
logsig_main(const float* __restrict__ sig, float* __restrict__ out) {
    __shared__ float sm[SMEM_X14];
    const int b = blockIdx.y;
    const float* __restrict__ row = sig + (size_t)b * SIG_SIZE;
    for (int i = threadIdx.x; i < SMEM_X14; i += blockDim.x) sm[i] = row[i];
    __syncthreads();

    const float* __restrict__ g5 = row + 4680;
    const float* __restrict__ g6 = row + 37448;
    float* __restrict__ orow = out + (size_t)b * NLYN;

    #pragma unroll 1
    for (int it = 0; it < 7; ++it) {
        int m = it * (32 * 256) + blockIdx.x * 256 + threadIdx.x;
        if (m >= NLYN) break;
        int f = d_table[m];
        float r;
        if      (f < 8)     r = eval_word<1>(sm, g5, g6, (unsigned)f);
        else if (f < 72)    r = eval_word<2>(sm, g5, g6, (unsigned)(f - 8));
        else if (f < 584)   r = eval_word<3>(sm, g5, g6, (unsigned)(f - 72));
        else if (f < 4680)  r = eval_word<4>(sm, g5, g6, (unsigned)(f - 584));
        else if (f < 37448) r = eval_word<5>(sm, g5, g6, (unsigned)(f - 4680));
        else                r = eval_word<6>(sm, g5, g6, (unsigned)(f - 37448));
        orow[m] = r;
    }
}

// ---------------------------------------------------------------------------
extern "C" void kernel_launch(void* const* d_in, const int* in_sizes, int n_in,
                              void* d_out, int out_size) {
    const float* sig = (const float*)d_in[0];
    float* out = (float*)d_out;

    k_count<<<K1_BLK, 256>>>();
    k_scanb<<<1, 256>>>();
    k_fill<<<K1_BLK, 256>>>();

    dim3 grid(32, BATCH);
    logsig_main<<<grid, 256>>>(sig, out);
}